// round 4
// baseline (speedup 1.0000x reference)
#include <cuda_runtime.h>

#define Nn 128
#define Ff 16
#define FP 32
#define NM1 127u
#define MAXB 64

// per-batch node scalars: S[b][0..127]=s1, S[b][128..255]=s2
__device__ float g_S[MAXB * 2 * Nn];

// ---- kernel 1: compute S (one block per batch, no redundancy) ----
__global__ void __launch_bounds__(128) compute_s(
    const float* __restrict__ x,
    const float* __restrict__ w,
    const float* __restrict__ a)
{
    __shared__ float v1[Ff], v2[Ff];
    const int tid = threadIdx.x;
    const int b   = blockIdx.x;

    // prefetch this node's 16 x values (coalesced, LDGs in flight over v-compute)
    float xr[Ff];
    const float* xb = x + (size_t)b * Ff * Nn + tid;
    #pragma unroll
    for (int f = 0; f < Ff; ++f)
        xr[f] = xb[f * Nn];

    // warp 0 computes v1/v2 = w^T a1 / w^T a2
    if (tid < 2 * Ff) {
        const int f = tid & (Ff - 1);
        const float* av = a + (tid < Ff ? 0 : FP);
        float acc = 0.f;
        #pragma unroll
        for (int g = 0; g < FP; ++g)
            acc += w[g * Ff + f] * av[g];
        if (tid < Ff) v1[f] = acc; else v2[f] = acc;
    }
    __syncthreads();

    float acc1 = 0.f, acc2 = 0.f;
    #pragma unroll
    for (int f = 0; f < Ff; ++f) {
        acc1 += xr[f] * v1[f];
        acc2 += xr[f] * v2[f];
    }
    g_S[b * 2 * Nn + tid]      = acc1;
    g_S[b * 2 * Nn + Nn + tid] = acc2;
}

// ---- kernel 2: pure gather, warp-per-(batch,row), no smem, no barriers ----
__global__ void __launch_bounds__(256) gather_out(
    float* __restrict__ out, int NR)
{
    const int warp   = (blockIdx.x * 256 + threadIdx.x) >> 5;
    const int lane   = threadIdx.x & 31;
    const int b      = warp >> 7;          // 128 rows per batch
    const unsigned r = warp & 127;

    const float* Sb = g_S + b * 2 * Nn;
    const float s1v = __ldg(Sb + r);       // broadcast within warp
    float* orow = out + (size_t)b * NR + r * NM1;

    // 127 outputs per row: k = lane, lane+32, lane+64, lane+96 (last partial)
    #pragma unroll
    for (int i = 0; i < 4; ++i) {
        const unsigned k = lane + 32 * i;
        if (k < NM1) {
            const unsigned s = k + (k >= r);
            orow[k] = s1v + __ldg(Sb + Nn + s);
        }
    }
}

extern "C" void kernel_launch(void* const* d_in, const int* in_sizes, int n_in,
                              void* d_out, int out_size) {
    const float* x = (const float*)d_in[0];
    const float* w = (const float*)d_in[1];
    const float* a = (const float*)d_in[2];
    float*     out = (float*)d_out;

    const int B  = in_sizes[0] / (Ff * Nn);   // x is (B, F, N)
    const int NR = in_sizes[3];               // N*(N-1) = 16256

    compute_s<<<B, 128>>>(x, w, a);
    const int nwarps  = B * Nn;               // one warp per (b, row)
    const int nblocks = (nwarps * 32 + 255) / 256;
    gather_out<<<nblocks, 256>>>(out, NR);
}

// round 5
// speedup vs baseline: 1.2330x; 1.2330x over previous
#include <cuda_runtime.h>

#define Nn 128
#define Ff 16
#define FP 32
#define NM1 127

__global__ void __launch_bounds__(512) gat_one(
    const float* __restrict__ x,
    const float* __restrict__ w,
    const float* __restrict__ a,
    float*       __restrict__ out,
    int NR)
{
    __shared__ float v1[Ff], v2[Ff];
    __shared__ float s1[Nn], s2[Nn + 1];   // +1 pad so s2[k+1] is always in-bounds
    const int tid = threadIdx.x;
    const int b   = blockIdx.y;

    // --- threads 0..127: issue x prefetch LDGs (latency overlapped below) ---
    float xr[Ff];
    if (tid < Nn) {
        const float* xb = x + (size_t)b * Ff * Nn + tid;
        #pragma unroll
        for (int f = 0; f < Ff; ++f)
            xr[f] = xb[f * Nn];
    }

    // --- warp 4 (threads 128..159) computes v1/v2 = w^T a1 / w^T a2 ---
    if (tid >= 128 && tid < 160) {
        const int t = tid - 128;
        const int f = t & (Ff - 1);
        const float* av = a + (t < Ff ? 0 : FP);
        float acc = 0.f;
        #pragma unroll
        for (int g = 0; g < FP; ++g)
            acc += w[g * Ff + f] * av[g];
        if (t < Ff) v1[f] = acc; else v2[f] = acc;
    }
    if (tid == 160) s2[Nn] = 0.f;          // pad
    __syncthreads();

    // --- s1[n] = x[b,:,n].v1 ; s2[n] = x[b,:,n].v2 ---
    if (tid < Nn) {
        float acc1 = 0.f, acc2 = 0.f;
        #pragma unroll
        for (int f = 0; f < Ff; ++f) {
            acc1 += xr[f] * v1[f];
            acc2 += xr[f] * v2[f];
        }
        s1[tid] = acc1;
        s2[tid] = acc2;
    }
    __syncthreads();

    // --- hot loop: this block writes rows [r0, r0+64) of batch b ---
    // thread layout: k = tid&127 (output column within row), rg = tid>>7 (row subgroup)
    const int k  = tid & (Nn - 1);
    const int rg = tid >> 7;               // 0..3
    const int r0 = blockIdx.x * (Nn / 2);  // 0 or 64

    // s2 values this thread can ever need live in two registers
    const float s2a = s2[k];
    const float s2b = s2[k + 1];

    float* ob = out + (size_t)b * NR;

    if (k < NM1) {
        #pragma unroll
        for (int i = 0; i < Nn / 2; i += 4) {
            const int r = r0 + i + rg;
            const float s1v = s1[r];                     // warp-broadcast LDS
            ob[r * NM1 + k] = s1v + (k >= r ? s2b : s2a);
        }
    }
}

extern "C" void kernel_launch(void* const* d_in, const int* in_sizes, int n_in,
                              void* d_out, int out_size) {
    const float* x = (const float*)d_in[0];
    const float* w = (const float*)d_in[1];
    const float* a = (const float*)d_in[2];
    float*     out = (float*)d_out;

    const int B  = in_sizes[0] / (Ff * Nn);   // x is (B, F, N)
    const int NR = in_sizes[3];               // N*(N-1) = 16256

    dim3 grid(2, B);                           // 128 blocks, one half-batch each
    gat_one<<<grid, 512>>>(x, w, a, out, NR);
}